// round 2
// baseline (speedup 1.0000x reference)
#include <cuda_runtime.h>

#define B_DIM 4
#define T_DIM 1024
#define VD    512
#define HALF  256
#define NL    64
#define C_DIM 256

// Scratch accumulator A[b][l][d] : 4*64*256 floats = 256 KB (fits easily in L2)
__device__ float g_A[B_DIM * NL * HALF];

// ---------------------------------------------------------------------------
// Kernel 0: zero the accumulator and the output (d_out is poisoned to 0xAA)
// ---------------------------------------------------------------------------
__global__ void vb_zero_kernel(float* __restrict__ out) {
    int i = blockIdx.x * blockDim.x + threadIdx.x;
    int stride = gridDim.x * blockDim.x;
    const int nA = B_DIM * NL * HALF;
    for (int j = i; j < nA; j += stride) g_A[j] = 0.0f;
    if (i < B_DIM * C_DIM) out[i] = 0.0f;
}

// ---------------------------------------------------------------------------
// Kernel 1: scatter phase
//   A[b, label[b,t], d] += scores[b,t] * weight[indices[b,t], off+d]
// Grid: (B*T / TOK_PER_BLK) blocks, 256 threads (thread = d).
// Each block handles 32 consecutive tokens (all within one batch row since
// T=1024 is a multiple of 32).
// ---------------------------------------------------------------------------
#define TOK_PER_BLK 32

__global__ void vb_scatter_kernel(const int*   __restrict__ indices,
                                  const float* __restrict__ scores,
                                  const int*   __restrict__ label,
                                  const int*   __restrict__ index_sel,
                                  const float* __restrict__ weight) {
    __shared__ int   s_idx[TOK_PER_BLK];
    __shared__ int   s_lab[TOK_PER_BLK];
    __shared__ float s_sc [TOK_PER_BLK];

    const int t0  = blockIdx.x * TOK_PER_BLK;
    const int tid = threadIdx.x;

    if (tid < TOK_PER_BLK) {
        int t = t0 + tid;
        s_idx[tid] = indices[t];
        s_lab[tid] = label[t];
        s_sc [tid] = scores[t];
    }
    __syncthreads();

    const int off = (index_sel[0] == 1) ? HALF : 0;
    const int b   = t0 / T_DIM;            // constant within block
    const int d   = tid;                    // 0..255

    // Unrolled so the compiler batches the independent gathers (MLP) ahead of
    // the atomics.
    #pragma unroll 8
    for (int j = 0; j < TOK_PER_BLK; j++) {
        float v = weight[s_idx[j] * VD + off + d] * s_sc[j];
        atomicAdd(&g_A[(b * NL + s_lab[j]) * HALF + d], v);
    }
}

// ---------------------------------------------------------------------------
// Kernel 2: reduction GEMM
//   out[b,c] += sum_{d in chunk} A[b, l, d] * W[l, off+d, c]
// Grid: NL * (HALF/DCHUNK) blocks; 256 threads (thread = c).
// ---------------------------------------------------------------------------
#define DCHUNK 64

__global__ void vb_gemm_kernel(const float* __restrict__ W,
                               const int*   __restrict__ index_sel,
                               float*       __restrict__ out) {
    const int l  = blockIdx.x / (HALF / DCHUNK);
    const int dc = blockIdx.x % (HALF / DCHUNK);
    const int d0 = dc * DCHUNK;
    const int c  = threadIdx.x;

    const int off = (index_sel[0] == 1) ? HALF : 0;

    __shared__ float sA[B_DIM][DCHUNK];
    {
        // 256 threads load the 4x64 A slice
        int b  = threadIdx.x / DCHUNK;
        int dd = threadIdx.x % DCHUNK;
        sA[b][dd] = g_A[(b * NL + l) * HALF + d0 + dd];
    }
    __syncthreads();

    float acc0 = 0.f, acc1 = 0.f, acc2 = 0.f, acc3 = 0.f;
    const float* Wp = W + ((l * VD) + off + d0) * C_DIM + c;

    #pragma unroll 8
    for (int d = 0; d < DCHUNK; d++) {
        float w = Wp[d * C_DIM];           // coalesced across threads (c)
        acc0 += sA[0][d] * w;
        acc1 += sA[1][d] * w;
        acc2 += sA[2][d] * w;
        acc3 += sA[3][d] * w;
    }

    atomicAdd(&out[0 * C_DIM + c], acc0);
    atomicAdd(&out[1 * C_DIM + c], acc1);
    atomicAdd(&out[2 * C_DIM + c], acc2);
    atomicAdd(&out[3 * C_DIM + c], acc3);
}

// ---------------------------------------------------------------------------
// Launch
// Inputs (metadata order): indices(int32 B*T), scores(f32 B*T),
//   W(f32 64*512*256), label(int32 B*T), index(int32 scalar),
//   weight(f32 262144*512). Output: f32 B*C = 1024.
// ---------------------------------------------------------------------------
extern "C" void kernel_launch(void* const* d_in, const int* in_sizes, int n_in,
                              void* d_out, int out_size) {
    const int*   indices   = (const int*)  d_in[0];
    const float* scores    = (const float*)d_in[1];
    const float* W         = (const float*)d_in[2];
    const int*   label     = (const int*)  d_in[3];
    const int*   index_sel = (const int*)  d_in[4];
    const float* weight    = (const float*)d_in[5];
    float*       out       = (float*)d_out;

    // Kernel 0: zero A (256KB) and out (1024 floats)
    vb_zero_kernel<<<256, 256>>>(out);

    // Kernel 1: scatter (128 blocks x 256 threads)
    vb_scatter_kernel<<<(B_DIM * T_DIM) / TOK_PER_BLK, 256>>>(
        indices, scores, label, index_sel, weight);

    // Kernel 2: GEMM reduction (256 blocks x 256 threads)
    vb_gemm_kernel<<<NL * (HALF / DCHUNK), 256>>>(W, index_sel, out);
}